// round 10
// baseline (speedup 1.0000x reference)
#include <cuda_runtime.h>
#include <cuda_bf16.h>
#include <cstdint>

#define C_DIM 2048
#define R_DIM 1024
#define B_DIM 16

#define CHUNK_ROWS 2
#define TOTAL_CHUNKS ((B_DIM * R_DIM) / CHUNK_ROWS)   /* 8192 */
#define NBUF 6
#define CHUNK_BYTES (CHUNK_ROWS * C_DIM * 4)          /* 16384 */
#define SMEM_TOTAL (NBUF * CHUNK_BYTES + 64)          /* 6 buffers + mbarriers */

#define GRID_BLOCKS 296                                /* 2 CTAs/SM * 148 SMs */
#define NGATHER (GRID_BLOCKS - 2)                      /* 294 persistent gatherers */

// Device-global scratch (no allocations allowed)
__device__ int g_sel_b[C_DIM];   // out col j reads input col g_sel_b[j]
__device__ int g_inv_r[R_DIM];   // input row q goes to output row g_inv_r[q]
__device__ int g_flag[2];        // prep-done flags (col, row); idempotent 0->1

// ---------------- PTX helpers ----------------
__device__ __forceinline__ uint32_t smem_u32(const void* p) {
    return (uint32_t)__cvta_generic_to_shared(p);
}
__device__ __forceinline__ void mbar_init(uint32_t a, uint32_t cnt) {
    asm volatile("mbarrier.init.shared.b64 [%0], %1;" :: "r"(a), "r"(cnt) : "memory");
}
__device__ __forceinline__ void mbar_expect_tx(uint32_t a, uint32_t bytes) {
    asm volatile("mbarrier.arrive.expect_tx.shared.b64 _, [%0], %1;"
                 :: "r"(a), "r"(bytes) : "memory");
}
__device__ __forceinline__ void mbar_wait(uint32_t a, uint32_t parity) {
    asm volatile(
        "{\n\t.reg .pred P;\n\t"
        "WAIT_%=:\n\t"
        "mbarrier.try_wait.parity.acquire.cta.shared::cta.b64 P, [%0], %1, 0x989680;\n\t"
        "@P bra.uni DONE_%=;\n\t"
        "bra.uni WAIT_%=;\n\t"
        "DONE_%=:\n\t}"
        :: "r"(a), "r"(parity) : "memory");
}
__device__ __forceinline__ void bulk_ld(uint32_t dst, const void* src,
                                        uint32_t bytes, uint32_t mbar) {
    asm volatile(
        "cp.async.bulk.shared::cluster.global.mbarrier::complete_tx::bytes [%0], [%1], %2, [%3];"
        :: "r"(dst), "l"(src), "r"(bytes), "r"(mbar) : "memory");
}

// ---------------- block-wide inclusive scan (1024 threads) ----------------
__device__ __forceinline__ void block_scan(int* a, int n, int tid, int* wsum) {
    const int lane = tid & 31, wid = tid >> 5;
    int v0 = 0, v1 = 0;
    const int i0 = 2 * tid;
    if (n == 2048) { v0 = a[i0]; v1 = a[i0 + 1]; }
    else           { v0 = a[tid]; }
    int s = v0 + v1;
    #pragma unroll
    for (int off = 1; off < 32; off <<= 1) {
        int y = __shfl_up_sync(0xffffffffu, s, off);
        if (lane >= off) s += y;
    }
    if (lane == 31) wsum[wid] = s;
    __syncthreads();
    if (wid == 0) {
        int t = wsum[lane];
        #pragma unroll
        for (int off = 1; off < 32; off <<= 1) {
            int y = __shfl_up_sync(0xffffffffu, t, off);
            if (lane >= off) t += y;
        }
        wsum[lane] = t;
    }
    __syncthreads();
    const int excl = (wid ? wsum[wid - 1] : 0) + s - (v0 + v1);
    if (n == 2048) { a[i0] = excl + v0; a[i0 + 1] = excl + v0 + v1; }
    else           { a[tid] = excl + v0; }
    __syncthreads();
}

// ---------------------------------------------------------------------------
// Persistent fused kernel, grid = 296 (2 CTAs/SM, single wave).
// Blocks 0,1: prep (dedup indices), then exit.
// Blocks 2..295: each owns a contiguous span of ~28 two-row chunks and runs
// one continuous 6-deep TMA pipeline over it — fill/drain paid once per slot.
// ---------------------------------------------------------------------------
__global__ void __launch_bounds__(1024, 2)
fused_kernel(const float* __restrict__ x, const float* __restrict__ wc,
             const float* __restrict__ wr, float* __restrict__ out)
{
    extern __shared__ char smem[];
    const int tid = threadIdx.x;

    if (blockIdx.x < 2) {
        // ================= PREP =================
        const bool  isC = (blockIdx.x == 0);
        const int   n   = isC ? C_DIM : R_DIM;
        const float* w  = isC ? wc : wr;

        int* sel         = (int*)smem;
        int* firstIdx    = sel + C_DIM;
        int* scanA       = firstIdx + C_DIM;
        int* emptyByRank = scanA + C_DIM;
        __shared__ int wsum[32];
        __shared__ int sh_E;

        const float upper = (float)(n - 1);
        if (n == 2048) {
            const int i0 = 2 * tid;
            sel[i0]     = __float2int_rn(fminf(fmaxf(w[i0],     0.0f), upper));
            sel[i0 + 1] = __float2int_rn(fminf(fmaxf(w[i0 + 1], 0.0f), upper));
            firstIdx[i0] = 0x7fffffff; firstIdx[i0 + 1] = 0x7fffffff;
        } else {
            sel[tid] = __float2int_rn(fminf(fmaxf(w[tid], 0.0f), upper));
            firstIdx[tid] = 0x7fffffff;
        }
        __syncthreads();
        for (int i = tid; i < n; i += 1024) atomicMin(&firstIdx[sel[i]], i);
        __syncthreads();

        // pass 1: scan EMPTY flags over values -> emptyByRank (descending)
        for (int v = tid; v < n; v += 1024)
            scanA[v] = (firstIdx[v] == 0x7fffffff) ? 1 : 0;
        __syncthreads();
        block_scan(scanA, n, tid, wsum);
        if (tid == 0) sh_E = scanA[n - 1];
        __syncthreads();
        const int E = sh_E;
        for (int v = tid; v < n; v += 1024) {
            if (firstIdx[v] == 0x7fffffff) {
                int asc = scanA[v] - 1;
                emptyByRank[E - 1 - asc] = v;   // slot 0 = largest empty value
            }
        }
        __syncthreads();

        // pass 2: scan DUP flags over indices -> duplicate rank
        for (int i = tid; i < n; i += 1024)
            scanA[i] = (firstIdx[sel[i]] != i) ? 1 : 0;
        __syncthreads();
        block_scan(scanA, n, tid, wsum);

        for (int i = tid; i < n; i += 1024) {
            bool dup = (firstIdx[sel[i]] != i);
            int v = dup ? emptyByRank[scanA[i] - 1] : sel[i];
            if (isC) g_sel_b[i] = v;     // column gather index
            else     g_inv_r[v] = i;     // inverse row permutation (v is a perm)
        }
        __threadfence();
        __syncthreads();
        if (tid == 0) {
            int* f = &g_flag[isC ? 0 : 1];
            asm volatile("st.release.gpu.global.b32 [%0], %1;"
                         :: "l"(f), "r"(1) : "memory");
        }
        return;
    }

    // ================= PERSISTENT GATHER / SCATTER =================
    const int base = (int)blockIdx.x - 2;                  // 0..NGATHER-1
    const int lo   = (int)(((long long)base       * TOTAL_CHUNKS) / NGATHER);
    const int hi   = (int)(((long long)(base + 1) * TOTAL_CHUNKS) / NGATHER);
    const int cnt  = hi - lo;                              // 27 or 28 chunks

    const uint32_t sbase = smem_u32(smem);
    const uint32_t mbarb = sbase + NBUF * CHUNK_BYTES;

    if (tid == 0) {
        #pragma unroll
        for (int p = 0; p < NBUF; p++) mbar_init(mbarb + 8 * p, 1);
        asm volatile("fence.proxy.async.shared::cta;" ::: "memory");
        // Prologue: fill the whole pipeline (up to 6 chunks, 96KB in flight).
        #pragma unroll
        for (int p = 0; p < NBUF; p++) {
            if (p < cnt) {
                mbar_expect_tx(mbarb + 8 * p, CHUNK_BYTES);
                bulk_ld(sbase + p * CHUNK_BYTES,
                        x + (size_t)(lo + p) * (CHUNK_ROWS * C_DIM),
                        CHUNK_BYTES, mbarb + 8 * p);
            }
        }
        // Wait for prep (overlapped with the loads above).
        int a, b;
        do {
            asm volatile("ld.acquire.gpu.global.b32 %0, [%1];" : "=r"(a) : "l"(&g_flag[0]));
            asm volatile("ld.acquire.gpu.global.b32 %0, [%1];" : "=r"(b) : "l"(&g_flag[1]));
        } while (!(a && b));
    }
    __syncthreads();

    // Fixed per-thread slot: row k within chunk (0/1), float4 column c4.
    const int c4 = tid & 511;
    const int k  = tid >> 9;
    const int4 bj = ((const int4*)g_sel_b)[c4];    // reused across all chunks

    for (int t = 0; t < cnt; t++) {
        const int buf_i = t % NBUF;
        const uint32_t mb = mbarb + 8 * buf_i;
        mbar_wait(mb, (t / NBUF) & 1);
        const float* srow = (const float*)(smem + buf_i * CHUNK_BYTES) + k * C_DIM;

        const int Q = (lo + t) * CHUNK_ROWS + k;             // input row (flat)
        const int orow = (Q & ~(R_DIM - 1)) | g_inv_r[Q & (R_DIM - 1)];
        float4 v;
        v.x = srow[bj.x]; v.y = srow[bj.y]; v.z = srow[bj.z]; v.w = srow[bj.w];
        __stwt(((float4*)out) + (size_t)orow * (C_DIM / 4) + c4, v);

        __syncthreads();   // buffer fully consumed by all threads

        if (tid == 0 && t + NBUF < cnt) {
            mbar_expect_tx(mb, CHUNK_BYTES);
            bulk_ld(sbase + buf_i * CHUNK_BYTES,
                    x + (size_t)(lo + t + NBUF) * (CHUNK_ROWS * C_DIM),
                    CHUNK_BYTES, mb);
        }
    }
}

extern "C" void kernel_launch(void* const* d_in, const int* in_sizes, int n_in,
                              void* d_out, int out_size) {
    const float* x  = (const float*)d_in[0];   // [16, 1024, 2048] f32
    const float* wc = (const float*)d_in[1];   // [2048] f32
    const float* wr = (const float*)d_in[2];   // [1024] f32
    float* out = (float*)d_out;

    cudaFuncSetAttribute(fused_kernel,
                         cudaFuncAttributeMaxDynamicSharedMemorySize, SMEM_TOTAL);
    fused_kernel<<<GRID_BLOCKS, 1024, SMEM_TOTAL>>>(x, wc, wr, out);
}

// round 11
// speedup vs baseline: 1.1229x; 1.1229x over previous
#include <cuda_runtime.h>
#include <cuda_bf16.h>
#include <cstdint>

#define C_DIM 2048
#define R_DIM 1024
#define B_DIM 16

#define ROWS_PER_BLOCK 8
#define CHUNK_ROWS 2
#define NCHUNKS (ROWS_PER_BLOCK / CHUNK_ROWS)      /* 4 — all front-issued */
#define CHUNK_BYTES (CHUNK_ROWS * C_DIM * 4)       /* 16384 */
#define SMEM_TOTAL (NCHUNKS * CHUNK_BYTES + 64)    /* 4 buffers + mbarriers */

// Device-global scratch (no allocations allowed)
__device__ int g_sel_b[C_DIM];   // out col j reads input col g_sel_b[j]
__device__ int g_inv_r[R_DIM];   // input row q goes to output row g_inv_r[q]
__device__ int g_flag[2];        // prep-done flags (col, row); idempotent 0->1

// ---------------- PTX helpers ----------------
__device__ __forceinline__ uint32_t smem_u32(const void* p) {
    return (uint32_t)__cvta_generic_to_shared(p);
}
__device__ __forceinline__ void mbar_init(uint32_t a, uint32_t cnt) {
    asm volatile("mbarrier.init.shared.b64 [%0], %1;" :: "r"(a), "r"(cnt) : "memory");
}
__device__ __forceinline__ void mbar_expect_tx(uint32_t a, uint32_t bytes) {
    asm volatile("mbarrier.arrive.expect_tx.shared.b64 _, [%0], %1;"
                 :: "r"(a), "r"(bytes) : "memory");
}
__device__ __forceinline__ void mbar_wait(uint32_t a, uint32_t parity) {
    asm volatile(
        "{\n\t.reg .pred P;\n\t"
        "WAIT_%=:\n\t"
        "mbarrier.try_wait.parity.acquire.cta.shared::cta.b64 P, [%0], %1, 0x989680;\n\t"
        "@P bra.uni DONE_%=;\n\t"
        "bra.uni WAIT_%=;\n\t"
        "DONE_%=:\n\t}"
        :: "r"(a), "r"(parity) : "memory");
}
__device__ __forceinline__ void bulk_ld(uint32_t dst, const void* src,
                                        uint32_t bytes, uint32_t mbar) {
    asm volatile(
        "cp.async.bulk.shared::cluster.global.mbarrier::complete_tx::bytes [%0], [%1], %2, [%3];"
        :: "r"(dst), "l"(src), "r"(bytes), "r"(mbar) : "memory");
}

// ---------------- block-wide inclusive scan (1024 threads) ----------------
__device__ __forceinline__ void block_scan(int* a, int n, int tid, int* wsum) {
    const int lane = tid & 31, wid = tid >> 5;
    int v0 = 0, v1 = 0;
    const int i0 = 2 * tid;
    if (n == 2048) { v0 = a[i0]; v1 = a[i0 + 1]; }
    else           { v0 = a[tid]; }
    int s = v0 + v1;
    #pragma unroll
    for (int off = 1; off < 32; off <<= 1) {
        int y = __shfl_up_sync(0xffffffffu, s, off);
        if (lane >= off) s += y;
    }
    if (lane == 31) wsum[wid] = s;
    __syncthreads();
    if (wid == 0) {
        int t = wsum[lane];
        #pragma unroll
        for (int off = 1; off < 32; off <<= 1) {
            int y = __shfl_up_sync(0xffffffffu, t, off);
            if (lane >= off) t += y;
        }
        wsum[lane] = t;
    }
    __syncthreads();
    const int excl = (wid ? wsum[wid - 1] : 0) + s - (v0 + v1);
    if (n == 2048) { a[i0] = excl + v0; a[i0 + 1] = excl + v0 + v1; }
    else           { a[tid] = excl + v0; }
    __syncthreads();
}

// ---------------------------------------------------------------------------
// Fused kernel. Blocks 0,1: prep (dedup indices). Blocks 2..: each handles 8
// input rows; ALL 4 bulk loads are front-issued in the prologue, so the
// consume loop has no refills and no __syncthreads — warps drift freely
// through {mbar_wait, smem gather, streaming STG.128}.
// ---------------------------------------------------------------------------
__global__ void __launch_bounds__(1024, 2)
fused_kernel(const float* __restrict__ x, const float* __restrict__ wc,
             const float* __restrict__ wr, float* __restrict__ out)
{
    extern __shared__ char smem[];
    const int tid = threadIdx.x;

    if (blockIdx.x < 2) {
        // ================= PREP =================
        const bool  isC = (blockIdx.x == 0);
        const int   n   = isC ? C_DIM : R_DIM;
        const float* w  = isC ? wc : wr;

        int* sel         = (int*)smem;
        int* firstIdx    = sel + C_DIM;
        int* scanA       = firstIdx + C_DIM;
        int* emptyByRank = scanA + C_DIM;
        __shared__ int wsum[32];
        __shared__ int sh_E;

        const float upper = (float)(n - 1);
        if (n == 2048) {
            const int i0 = 2 * tid;
            sel[i0]     = __float2int_rn(fminf(fmaxf(w[i0],     0.0f), upper));
            sel[i0 + 1] = __float2int_rn(fminf(fmaxf(w[i0 + 1], 0.0f), upper));
            firstIdx[i0] = 0x7fffffff; firstIdx[i0 + 1] = 0x7fffffff;
        } else {
            sel[tid] = __float2int_rn(fminf(fmaxf(w[tid], 0.0f), upper));
            firstIdx[tid] = 0x7fffffff;
        }
        __syncthreads();
        for (int i = tid; i < n; i += 1024) atomicMin(&firstIdx[sel[i]], i);
        __syncthreads();

        // pass 1: scan EMPTY flags over values -> emptyByRank (descending)
        for (int v = tid; v < n; v += 1024)
            scanA[v] = (firstIdx[v] == 0x7fffffff) ? 1 : 0;
        __syncthreads();
        block_scan(scanA, n, tid, wsum);
        if (tid == 0) sh_E = scanA[n - 1];
        __syncthreads();
        const int E = sh_E;
        for (int v = tid; v < n; v += 1024) {
            if (firstIdx[v] == 0x7fffffff) {
                int asc = scanA[v] - 1;
                emptyByRank[E - 1 - asc] = v;   // slot 0 = largest empty value
            }
        }
        __syncthreads();

        // pass 2: scan DUP flags over indices -> duplicate rank
        for (int i = tid; i < n; i += 1024)
            scanA[i] = (firstIdx[sel[i]] != i) ? 1 : 0;
        __syncthreads();
        block_scan(scanA, n, tid, wsum);

        for (int i = tid; i < n; i += 1024) {
            bool dup = (firstIdx[sel[i]] != i);
            int v = dup ? emptyByRank[scanA[i] - 1] : sel[i];
            if (isC) g_sel_b[i] = v;     // column gather index
            else     g_inv_r[v] = i;     // inverse row permutation (v is a perm)
        }
        __threadfence();
        __syncthreads();
        if (tid == 0) {
            int* f = &g_flag[isC ? 0 : 1];
            asm volatile("st.release.gpu.global.b32 [%0], %1;"
                         :: "l"(f), "r"(1) : "memory");
        }
        return;
    }

    // ================= GATHER / SCATTER =================
    const int q0 = (int)(blockIdx.x - 2) * ROWS_PER_BLOCK;   // first input row
    const uint32_t sbase = smem_u32(smem);
    const uint32_t mbarb = sbase + NCHUNKS * CHUNK_BYTES;

    if (tid == 0) {
        #pragma unroll
        for (int p = 0; p < NCHUNKS; p++) mbar_init(mbarb + 8 * p, 1);
        asm volatile("fence.proxy.async.shared::cta;" ::: "memory");
        // Prologue: the block's ENTIRE data (64KB) issued as 4 bulk loads.
        #pragma unroll
        for (int p = 0; p < NCHUNKS; p++) {
            mbar_expect_tx(mbarb + 8 * p, CHUNK_BYTES);
            bulk_ld(sbase + p * CHUNK_BYTES,
                    x + (size_t)(q0 + p * CHUNK_ROWS) * C_DIM,
                    CHUNK_BYTES, mbarb + 8 * p);
        }
        // Wait for prep (overlapped with the loads above).
        int a, b;
        do {
            asm volatile("ld.acquire.gpu.global.b32 %0, [%1];" : "=r"(a) : "l"(&g_flag[0]));
            asm volatile("ld.acquire.gpu.global.b32 %0, [%1];" : "=r"(b) : "l"(&g_flag[1]));
        } while (!(a && b));
    }
    __syncthreads();

    // Fixed per-thread slot: row k within chunk (0/1), float4 column c4.
    const int c4 = tid & 511;
    const int k  = tid >> 9;
    const int4 bj = ((const int4*)g_sel_b)[c4];    // reused across all chunks

    // Barrier-free consume: buffers are never reused (parity always 0).
    #pragma unroll
    for (int c = 0; c < NCHUNKS; c++) {
        mbar_wait(mbarb + 8 * c, 0);
        const float* srow = (const float*)(smem + c * CHUNK_BYTES) + k * C_DIM;

        const int Q = q0 + c * CHUNK_ROWS + k;               // input row (flat)
        const int orow = (Q & ~(R_DIM - 1)) | g_inv_r[Q & (R_DIM - 1)];
        float4 v;
        v.x = srow[bj.x]; v.y = srow[bj.y]; v.z = srow[bj.z]; v.w = srow[bj.w];
        __stwt(((float4*)out) + (size_t)orow * (C_DIM / 4) + c4, v);
    }
}

extern "C" void kernel_launch(void* const* d_in, const int* in_sizes, int n_in,
                              void* d_out, int out_size) {
    const float* x  = (const float*)d_in[0];   // [16, 1024, 2048] f32
    const float* wc = (const float*)d_in[1];   // [2048] f32
    const float* wr = (const float*)d_in[2];   // [1024] f32
    float* out = (float*)d_out;

    cudaFuncSetAttribute(fused_kernel,
                         cudaFuncAttributeMaxDynamicSharedMemorySize, SMEM_TOTAL);
    const int grid = 2 + (B_DIM * R_DIM) / ROWS_PER_BLOCK;   // 2050
    fused_kernel<<<grid, 1024, SMEM_TOTAL>>>(x, wc, wr, out);
}